// round 5
// baseline (speedup 1.0000x reference)
#include <cuda_runtime.h>
#include <math.h>
#include <stdint.h>

typedef unsigned long long ull;

// ---------------- constants ----------------
#define TT    24          // timesteps per CTA tile (240/24 = 10 tiles)
#define XSTR  28          // smem row stride for [180][TT] tiles
#define KC    12          // K-chunk staged in smem (180 = 15 * 12)
#define NCH   15
#define HPAD  192         // padded h-slots per k row in smem weight tiles
#define THR1  192         // 3 t-groups x 64 h-lanes

// smem layout (bytes)
#define SMEM_XS   0
#define SMEM_HS   20160                      // 180*28*4
#define SMEM_WS4  40320                      // + 180*28*4
#define SMEM_WS2  77184                      // + KC*192*4*4 = 36864
#define SMEM_RA   95616                      // + KC*192*2*4 = 18432
#define SMEM_RM   96384                      // + 8*24*4
#define SMEM_RS   96480
#define SMEM1_TOTAL 96576

// ---------------- device scratch (static allocation only) ----------------
__device__ float g_Wenc4[180 * 180 * 4];     // [k][h][{i,i,g,g}]
__device__ float g_Wenc2[180 * 180 * 2];     // [k][h][{o,o}]
__device__ float g_Wdec4[180 * 180 * 4];
__device__ float g_Wdec2[180 * 180 * 2];
__device__ float g_bencP[180 * 4];           // [h][{i,g,o,pad}]
__device__ float g_bdecP[180 * 4];
__device__ float g_hdec[88473600];           // [2048][240][180]
__device__ float g_part[16 * 2048 * 40];     // split-K partial logits

// ---------------- f32x2 helpers ----------------
__device__ __forceinline__ ull ffma2(ull a, ull b, ull c) {
    ull d;
    asm("fma.rn.f32x2 %0, %1, %2, %3;" : "=l"(d) : "l"(a), "l"(b), "l"(c));
    return d;
}
__device__ __forceinline__ float2 unpackf2(ull v) {
    float2 r;
    asm("mov.b64 {%0, %1}, %2;" : "=f"(r.x), "=f"(r.y) : "l"(v));
    return r;
}
__device__ __forceinline__ float sigmoidf_(float v) { return 1.f / (1.f + expf(-v)); }

// ---------------- kernel P: repack weights k-major, pre-duplicated pairs ----------------
__global__ void pack_weights(const float* __restrict__ We, const float* __restrict__ bie,
                             const float* __restrict__ bhe, const float* __restrict__ Wd,
                             const float* __restrict__ bid, const float* __restrict__ bhd) {
    int idx = blockIdx.x * blockDim.x + threadIdx.x;
    int stride = gridDim.x * blockDim.x;
    for (int i = idx; i < 180 * 180; i += stride) {
        int k = i / 180, h = i % 180;
        float ei = We[h * 180 + k];
        float eg = We[(360 + h) * 180 + k];
        float eo = We[(540 + h) * 180 + k];
        float di = Wd[h * 180 + k];
        float dg = Wd[(360 + h) * 180 + k];
        float dof = Wd[(540 + h) * 180 + k];
        *(float4*)&g_Wenc4[(size_t)i * 4] = make_float4(ei, ei, eg, eg);
        *(float2*)&g_Wenc2[(size_t)i * 2] = make_float2(eo, eo);
        *(float4*)&g_Wdec4[(size_t)i * 4] = make_float4(di, di, dg, dg);
        *(float2*)&g_Wdec2[(size_t)i * 2] = make_float2(dof, dof);
    }
    for (int h = idx; h < 180; h += stride) {
        g_bencP[h * 4 + 0] = bie[h] + bhe[h];
        g_bencP[h * 4 + 1] = bie[360 + h] + bhe[360 + h];
        g_bencP[h * 4 + 2] = bie[540 + h] + bhe[540 + h];
        g_bencP[h * 4 + 3] = 0.f;
        g_bdecP[h * 4 + 0] = bid[h] + bhd[h];
        g_bdecP[h * 4 + 1] = bid[360 + h] + bhd[360 + h];
        g_bdecP[h * 4 + 2] = bid[540 + h] + bhd[540 + h];
        g_bdecP[h * 4 + 3] = 0.f;
    }
}

// ---------------- kernel 1: fused enc-GEMM -> softmax -> dec-GEMM -> hdec ----------------
__global__ void __launch_bounds__(THR1, 2) fused_encdec(const float* __restrict__ x) {
    extern __shared__ char smem_raw[];
    float(*Xs)[XSTR] = reinterpret_cast<float(*)[XSTR]>(smem_raw + SMEM_XS);
    float(*Hs)[XSTR] = reinterpret_cast<float(*)[XSTR]>(smem_raw + SMEM_HS);
    float* Ws4 = reinterpret_cast<float*>(smem_raw + SMEM_WS4);   // [KC][HPAD][4]
    float* Ws2 = reinterpret_cast<float*>(smem_raw + SMEM_WS2);   // [KC][HPAD][2]
    float(*redA)[24] = reinterpret_cast<float(*)[24]>(smem_raw + SMEM_RA);
    float* redM = reinterpret_cast<float*>(smem_raw + SMEM_RM);
    float* redS = reinterpret_cast<float*>(smem_raw + SMEM_RS);

    const int b  = blockIdx.y;
    const int t0 = blockIdx.x * TT;
    const int tid = threadIdx.x;
    const int tx = tid / 64;   // 0..2 : t-group of 8 timesteps
    const int ty = tid % 64;   // h lanes

    // load input tile: Xs[f][t] = x[b][f][t0+t]   (x is [B,180,240] contiguous)
    for (int i = tid; i < 180 * TT; i += THR1) {
        int f = i / TT, t = i % TT;
        Xs[f][t] = x[((size_t)b * 180 + f) * 240 + t0 + t];
    }

    for (int pass = 0; pass < 2; pass++) {
        const float* W4g = pass ? g_Wdec4 : g_Wenc4;
        const float* W2g = pass ? g_Wdec2 : g_Wenc2;
        ull acc[3][3][4];
#pragma unroll
        for (int j = 0; j < 3; j++)
#pragma unroll
            for (int g = 0; g < 3; g++)
#pragma unroll
                for (int v = 0; v < 4; v++) acc[j][g][v] = 0ull;

        for (int c = 0; c < NCH; c++) {
            __syncthreads();  // protect Ws reuse; also orders Xs producers
            // stage W chunk into padded smem rows
            {
                const float4* src4 = (const float4*)(W4g + (size_t)c * KC * 720);
                for (int i = tid; i < KC * 180; i += THR1) {
                    int kk = i / 180, h = i % 180;
                    *(float4*)&Ws4[(kk * HPAD + h) * 4] = src4[i];
                }
                const float4* src2 = (const float4*)(W2g + (size_t)c * KC * 360);
                for (int i = tid; i < KC * 90; i += THR1) {
                    int kk = i / 90, h2 = i % 90;
                    *(float4*)&Ws2[(kk * HPAD + h2 * 2) * 2] = src2[i];
                }
            }
            __syncthreads();
#pragma unroll 4
            for (int kk = 0; kk < KC; kk++) {
                const int k = c * KC + kk;
                ulonglong2 xa = *(const ulonglong2*)&Xs[k][tx * 8];
                ulonglong2 xb = *(const ulonglong2*)&Xs[k][tx * 8 + 4];
                ull xs0 = xa.x, xs1 = xa.y, xs2 = xb.x, xs3 = xb.y;
#pragma unroll
                for (int j = 0; j < 3; j++) {
                    const int h = ty + 64 * j;
                    ulonglong2 wig = *(const ulonglong2*)&Ws4[(kk * HPAD + h) * 4];
                    ull wo = *(const ull*)&Ws2[(kk * HPAD + h) * 2];
                    ull wi = wig.x, wg = wig.y;
                    acc[j][0][0] = ffma2(xs0, wi, acc[j][0][0]);
                    acc[j][0][1] = ffma2(xs1, wi, acc[j][0][1]);
                    acc[j][0][2] = ffma2(xs2, wi, acc[j][0][2]);
                    acc[j][0][3] = ffma2(xs3, wi, acc[j][0][3]);
                    acc[j][1][0] = ffma2(xs0, wg, acc[j][1][0]);
                    acc[j][1][1] = ffma2(xs1, wg, acc[j][1][1]);
                    acc[j][1][2] = ffma2(xs2, wg, acc[j][1][2]);
                    acc[j][1][3] = ffma2(xs3, wg, acc[j][1][3]);
                    acc[j][2][0] = ffma2(xs0, wo, acc[j][2][0]);
                    acc[j][2][1] = ffma2(xs1, wo, acc[j][2][1]);
                    acc[j][2][2] = ffma2(xs2, wo, acc[j][2][2]);
                    acc[j][2][3] = ffma2(xs3, wo, acc[j][2][3]);
                }
            }
        }

        // activations: c = sig(i)*tanh(g); h = sig(o)*tanh(c)
        const float* bp = pass ? g_bdecP : g_bencP;
#pragma unroll
        for (int j = 0; j < 3; j++) {
            int h = ty + 64 * j;
            if (h < 180) {
                float4 bb = *(const float4*)&bp[h * 4];
#pragma unroll
                for (int v = 0; v < 4; v++) {
                    float2 fi = unpackf2(acc[j][0][v]);
                    float2 fg = unpackf2(acc[j][1][v]);
                    float2 fo = unpackf2(acc[j][2][v]);
                    float c0 = sigmoidf_(fi.x + bb.x) * tanhf(fg.x + bb.y);
                    float c1 = sigmoidf_(fi.y + bb.x) * tanhf(fg.y + bb.y);
                    float h0 = sigmoidf_(fo.x + bb.z) * tanhf(c0);
                    float h1 = sigmoidf_(fo.y + bb.z) * tanhf(c1);
                    Hs[h][tx * 8 + 2 * v]     = h0;
                    Hs[h][tx * 8 + 2 * v + 1] = h1;
                }
            }
        }
        __syncthreads();

        if (pass == 0) {
            // softmax over h (180) per column t, result -> Xs (decoder input)
            int col = tid % 24, sl = tid / 24;            // 24 cols x 8 slices
            int h0 = sl * 23, h1 = min(180, h0 + 23);
            float m = -1e30f;
            for (int h = h0; h < h1; h++) m = fmaxf(m, Hs[h][col]);
            redA[sl][col] = m;
            __syncthreads();
            if (sl == 0) {
                float mm = redA[0][col];
#pragma unroll
                for (int s = 1; s < 8; s++) mm = fmaxf(mm, redA[s][col]);
                redM[col] = mm;
            }
            __syncthreads();
            float mm = redM[col];
            float s = 0.f;
            for (int h = h0; h < h1; h++) {
                float e = expf(Hs[h][col] - mm);
                Hs[h][col] = e;                 // cache exp; each (sl,col) owns range
                s += e;
            }
            redA[sl][col] = s;
            __syncthreads();
            if (sl == 0) {
                float ss = 0.f;
#pragma unroll
                for (int s2 = 0; s2 < 8; s2++) ss += redA[s2][col];
                redS[col] = 1.f / ss;
            }
            __syncthreads();
            float inv = redS[col];
            for (int h = h0; h < h1; h++) Xs[h][col] = Hs[h][col] * inv;
            // next pass's first __syncthreads() orders these writes vs readers
        } else {
            // write h_dec: g_hdec[b][t0+t][h]
            for (int i = tid; i < 180 * TT; i += THR1) {
                int h = i % 180, t = i / 180;
                g_hdec[((size_t)b * 240 + t0 + t) * 180 + h] = Hs[h][t];
            }
        }
    }
}

// ---------------- kernel C: output GEMM, split-K partials ----------------
__global__ void __launch_bounds__(256) out_gemm(const float* __restrict__ Wout) {
    __shared__ float Hc[64][62];
    __shared__ float Wc[40][62];
    const int ks = blockIdx.x;        // 0..15
    const int b0 = blockIdx.y * 64;   // 0..31 tiles
    const int k0 = ks * 2700;
    const int tid = threadIdx.x;
    const int bg = tid % 32;
    const int ng = tid / 32;          // 0..7 -> 5 n each

    ull acc2[2][5];
#pragma unroll
    for (int bi = 0; bi < 2; bi++)
#pragma unroll
        for (int q = 0; q < 5; q++) acc2[bi][q] = 0ull;

    for (int c = 0; c < 45; c++) {
        __syncthreads();
        const int kb = k0 + c * 60;
        for (int i = tid; i < 64 * 60; i += 256) {
            int bb = i / 60, k = i % 60;
            Hc[bb][k] = g_hdec[(size_t)(b0 + bb) * 43200 + kb + k];
        }
        for (int i = tid; i < 40 * 60; i += 256) {
            int n = i / 60, k = i % 60;
            Wc[n][k] = Wout[(size_t)n * 43200 + kb + k];
        }
        __syncthreads();
#pragma unroll 6
        for (int kp = 0; kp < 30; kp++) {
            ull h0 = *(const ull*)&Hc[bg][kp * 2];
            ull h1 = *(const ull*)&Hc[bg + 32][kp * 2];
#pragma unroll
            for (int q = 0; q < 5; q++) {
                ull w = *(const ull*)&Wc[ng * 5 + q][kp * 2];
                acc2[0][q] = ffma2(h0, w, acc2[0][q]);
                acc2[1][q] = ffma2(h1, w, acc2[1][q]);
            }
        }
    }
#pragma unroll
    for (int bi = 0; bi < 2; bi++)
#pragma unroll
        for (int q = 0; q < 5; q++) {
            float2 p = unpackf2(acc2[bi][q]);
            g_part[((size_t)ks * 2048 + b0 + bg + 32 * bi) * 40 + ng * 5 + q] = p.x + p.y;
        }
}

// ---------------- kernel D: reduce split-K + bias + grouped softmax ----------------
__global__ void reduce_softmax(const float* __restrict__ bout, float* __restrict__ out) {
    __shared__ float sm[40];
    const int b = blockIdx.x;
    const int n = threadIdx.x;  // 0..39
    float l = bout[n];
#pragma unroll
    for (int ks = 0; ks < 16; ks++) l += g_part[((size_t)ks * 2048 + b) * 40 + n];
    sm[n] = l;
    __syncthreads();
    const int g0 = (n / 10) * 10;
    float m = sm[g0];
#pragma unroll
    for (int i = 1; i < 10; i++) m = fmaxf(m, sm[g0 + i]);
    float s = 0.f;
#pragma unroll
    for (int i = 0; i < 10; i++) s += expf(sm[g0 + i] - m);
    out[(size_t)b * 40 + n] = expf(l - m) / s;
}

// ---------------- launcher ----------------
extern "C" void kernel_launch(void* const* d_in, const int* in_sizes, int n_in,
                              void* d_out, int out_size) {
    const float* x    = (const float*)d_in[0];
    const float* Wenc = (const float*)d_in[1];
    const float* bie  = (const float*)d_in[2];
    const float* bhe  = (const float*)d_in[3];
    const float* Wdec = (const float*)d_in[4];
    const float* bid  = (const float*)d_in[5];
    const float* bhd  = (const float*)d_in[6];
    const float* Wout = (const float*)d_in[7];
    const float* bout = (const float*)d_in[8];
    float* out = (float*)d_out;

    cudaFuncSetAttribute(fused_encdec, cudaFuncAttributeMaxDynamicSharedMemorySize, SMEM1_TOTAL);

    pack_weights<<<128, 256>>>(Wenc, bie, bhe, Wdec, bid, bhd);
    fused_encdec<<<dim3(10, 2048), THR1, SMEM1_TOTAL>>>(x);
    out_gemm<<<dim3(16, 32), 256>>>(Wout);
    reduce_softmax<<<2048, 40>>>(bout, out);
}

// round 8
// speedup vs baseline: 2.6902x; 2.6902x over previous
#include <cuda_runtime.h>
#include <cuda_bf16.h>
#include <math.h>
#include <stdint.h>

typedef unsigned long long ull;

// ===================== helpers =====================
__device__ __forceinline__ uint32_t smem_u32(const void* p) {
    uint32_t a;
    asm("{ .reg .u64 t; cvta.to.shared.u64 t, %1; cvt.u32.u64 %0, t; }" : "=r"(a) : "l"(p));
    return a;
}

#define LOG2E 1.4426950408889634f
__device__ __forceinline__ float ex2f(float x) { float r; asm("ex2.approx.ftz.f32 %0, %1;" : "=f"(r) : "f"(x)); return r; }
__device__ __forceinline__ float rcpf(float x) { float r; asm("rcp.approx.ftz.f32 %0, %1;" : "=f"(r) : "f"(x)); return r; }
__device__ __forceinline__ float sigf(float x)  { return rcpf(1.f + ex2f(-x * LOG2E)); }
__device__ __forceinline__ float tanhf_(float x) { return 2.f * rcpf(1.f + ex2f(-2.f * x * LOG2E)) - 1.f; }

// mma.sync m16n8k16 bf16 (sm_80+, no arch suffix)
__device__ __forceinline__ void mma16816(float* c, const uint32_t* a, const uint32_t* b) {
    asm volatile(
        "mma.sync.aligned.m16n8k16.row.col.f32.bf16.bf16.f32 "
        "{%0,%1,%2,%3}, {%4,%5,%6,%7}, {%8,%9}, {%0,%1,%2,%3};"
        : "+f"(c[0]), "+f"(c[1]), "+f"(c[2]), "+f"(c[3])
        : "r"(a[0]), "r"(a[1]), "r"(a[2]), "r"(a[3]), "r"(b[0]), "r"(b[1]));
}
#define LDSM4(r, a) \
    asm volatile("ldmatrix.sync.aligned.m8n8.x4.shared.b16 {%0,%1,%2,%3}, [%4];" \
        : "=r"((r)[0]), "=r"((r)[1]), "=r"((r)[2]), "=r"((r)[3]) : "r"(a))
#define LDSM2(r, a) \
    asm volatile("ldmatrix.sync.aligned.m8n8.x2.shared.b16 {%0,%1}, [%2];" \
        : "=r"((r)[0]), "=r"((r)[1]) : "r"(a))

#define CP16(dst, src) \
    asm volatile("cp.async.cg.shared.global [%0], [%1], 16;" :: "r"(dst), "l"(src) : "memory")
#define CP_COMMIT() asm volatile("cp.async.commit_group;" ::: "memory")
#define CP_WAIT1()  asm volatile("cp.async.wait_group 1;" ::: "memory")
#define CP_WAIT0()  asm volatile("cp.async.wait_group 0;" ::: "memory")

// ===================== global scratch =====================
// packed weights: [matgate 6][plane hi/lo][n 192][k 192] bf16
__device__ __nv_bfloat16 g_Wpk[6 * 2 * 192 * 192];
__device__ float g_bias[6 * 192];            // [matgate][n], zero-padded
__device__ float g_hdec[88473600];           // [2048][240][180]
__device__ float g_part[16 * 2048 * 40];

// ===================== smem layout (bytes) =====================
// A: 2 planes x [48 rows][200 bf16] (400B rows, conflict-free ldmatrix)
#define OA    0
#define APL   19200
// B: 2 slots x 2 planes x [192 n][72 bf16] (144B rows)
#define OB    38400
#define BSLOT 55296
#define BPL   27648
// cbuf: [192 n][52 t] fp32
#define OC    148992
// red: redM[192], redS[192]
#define ORED  188928
#define SMEM_TOT 190464

// ===================== prep: pack weights (bf16 hi/lo planes) + bias =====================
__global__ void prep_weights(const float* __restrict__ We, const float* __restrict__ bie,
                             const float* __restrict__ bhe, const float* __restrict__ Wd,
                             const float* __restrict__ bid, const float* __restrict__ bhd) {
    const int gb[3] = {0, 360, 540};   // torch gates i,f,g,o -> keep i,g,o (f-gate dead: c_prev=0)
    int idx = blockIdx.x * blockDim.x + threadIdx.x;
    int stride = gridDim.x * blockDim.x;
    for (int i = idx; i < 6 * 192 * 192; i += stride) {
        int k = i % 192, n = (i / 192) % 192, g = (i / 36864) % 3, mat = i / 110592;
        float v = 0.f;
        if (n < 180 && k < 180) v = (mat ? Wd : We)[(gb[g] + n) * 180 + k];
        __nv_bfloat16 h = __float2bfloat16(v);
        __nv_bfloat16 l = __float2bfloat16(v - __bfloat162float(h));
        size_t base = (size_t)(mat * 3 + g) * 2 * 36864 + (size_t)n * 192 + k;
        g_Wpk[base] = h;
        g_Wpk[base + 36864] = l;
    }
    for (int i = idx; i < 6 * 192; i += stride) {
        int n = i % 192, g = (i / 192) % 3, mat = i / 576;
        float v = 0.f;
        if (n < 180) v = (mat ? bid : bie)[gb[g] + n] + (mat ? bhd : bhe)[gb[g] + n];
        g_bias[(mat * 3 + g) * 192 + n] = v;
    }
}

// ===================== B chunk staging via cp.async =====================
__device__ __forceinline__ void stage_chunk(uint32_t sb, int tid, int c) {
    int mg = c / 3, kc = c % 3;              // matgate 0..5, k-chunk 0..2
    const char* base = (const char*)g_Wpk + (size_t)mg * 147456;   // 2*36864*2B
    uint32_t dstb = sb + OB + (uint32_t)(c & 1) * BSLOT;
#pragma unroll
    for (int it = 0; it < 12; it++) {
        int idx = tid + it * 256;            // 0..3071
        int j = idx & 7;                     // 16B piece within 128B row chunk
        int rowp = idx >> 3;                 // 0..383
        int p = rowp >= 192;
        int n = rowp - p * 192;
        const void* src = base + (size_t)p * 73728 + (size_t)n * 384 + kc * 128 + j * 16;
        uint32_t dst = dstb + (uint32_t)p * BPL + (uint32_t)n * 144 + (uint32_t)j * 16;
        CP16(dst, src);
    }
}

// ===================== fused enc -> softmax -> dec (mma.sync bf16 split) =====================
__global__ void __launch_bounds__(256) fused_encdec(const float* __restrict__ x) {
    extern __shared__ char sm[];
    const uint32_t sb = smem_u32(sm);
    float* C = (float*)(sm + OC);
    float* redM = (float*)(sm + ORED);
    float* redS = redM + 192;
    const int tid = threadIdx.x, lane = tid & 31, wid = tid >> 5;
    const int b = blockIdx.y, t0 = blockIdx.x * 48;

    // Build A planes from x[b][k][t0+t]  (x is [B,180,240] contiguous; f=c*60+hh matches k)
    for (int i = tid; i < 192 * 48; i += 256) {
        int k = i / 48, t = i % 48;
        float v = (k < 180) ? x[((size_t)b * 180 + k) * 240 + t0 + t] : 0.f;
        __nv_bfloat16 h = __float2bfloat16(v);
        __nv_bfloat16 l = __float2bfloat16(v - __bfloat162float(h));
        *(__nv_bfloat16*)(sm + OA + t * 400 + k * 2) = h;
        *(__nv_bfloat16*)(sm + OA + APL + t * 400 + k * 2) = l;
    }

    // ldmatrix per-lane offsets
    const int rit = lane & 7, grp = lane >> 3;
    const uint32_t aoff = (uint32_t)((rit + (grp & 1) * 8) * 400 + (grp >> 1) * 16);
    const int l2 = lane & 15;
    const uint32_t boff = (uint32_t)((l2 & 7) * 144 + (l2 >> 3) * 16);

    stage_chunk(sb, tid, 0);
    CP_COMMIT();

    int c = 0;
    float sval[36];
    for (int mat = 0; mat < 2; mat++) {
        for (int g = 0; g < 3; g++) {
            float acc[36];
#pragma unroll
            for (int v = 0; v < 36; v++) acc[v] = 0.f;

            for (int kc = 0; kc < 3; kc++, c++) {
                if (c + 1 < 18) { stage_chunk(sb, tid, c + 1); CP_COMMIT(); CP_WAIT1(); }
                else CP_WAIT0();
                __syncthreads();   // chunk c visible to all; also orders A writes (x build / softmax)
                uint32_t Bbase = sb + OB + (uint32_t)(c & 1) * BSLOT;
#pragma unroll
                for (int s = 0; s < 4; s++) {
                    const int k0 = kc * 64 + s * 16;       // global k for A
                    uint32_t Ah[3][4], Al[3][4];
#pragma unroll
                    for (int mi = 0; mi < 3; mi++) {
                        uint32_t a = sb + OA + (uint32_t)(mi * 6400) + (uint32_t)(k0 * 2) + aoff;
                        LDSM4(Ah[mi], a);
                        LDSM4(Al[mi], a + APL);
                    }
                    uint32_t Bh[3][2], Bl[3][2];
#pragma unroll
                    for (int ni = 0; ni < 3; ni++) {
                        uint32_t ba = Bbase + (uint32_t)((wid * 24 + ni * 8) * 144) +
                                      (uint32_t)(s * 32) + boff;
                        LDSM2(Bh[ni], ba);
                        LDSM2(Bl[ni], ba + BPL);
                    }
#pragma unroll
                    for (int mi = 0; mi < 3; mi++)
#pragma unroll
                        for (int ni = 0; ni < 3; ni++) {
                            float* cc = &acc[(mi * 3 + ni) * 4];
                            mma16816(cc, Ah[mi], Bh[ni]);   // hi*hi
                            mma16816(cc, Ah[mi], Bl[ni]);   // hi*lo
                            mma16816(cc, Al[mi], Bh[ni]);   // lo*hi
                        }
                }
                __syncthreads();   // all warps done with slot (c&1) before it is overwritten
            }

            // ---- gate epilogue (thread<->element mapping identical across gates) ----
            const float* bias = g_bias + (mat * 3 + g) * 192;
#pragma unroll
            for (int mi = 0; mi < 3; mi++)
#pragma unroll
                for (int ni = 0; ni < 3; ni++) {
                    int nb = wid * 24 + ni * 8 + (lane & 3) * 2;
                    float b0 = __ldg(bias + nb), b1 = __ldg(bias + nb + 1);
#pragma unroll
                    for (int r = 0; r < 4; r++) {
                        int v = (mi * 3 + ni) * 4 + r;
                        float bb = (r & 1) ? b1 : b0;
                        if (g == 0) {
                            sval[v] = sigf(acc[v] + bb);                       // sig(i)
                        } else if (g == 1) {
                            sval[v] = tanhf_(sval[v] * tanhf_(acc[v] + bb));   // tanh(c)
                        } else {
                            int t = mi * 16 + (lane >> 2) + ((r >> 1) & 1) * 8;
                            int n = nb + (r & 1);
                            C[n * 52 + t] = sigf(acc[v] + bb) * sval[v];       // h
                        }
                    }
                }

            if (g == 2) {
                __syncthreads();   // C complete
                if (mat == 0) {
                    // softmax over n (0..179) per t; rewrite A planes with decoder input
                    int t = tid >> 2, sl = tid & 3, n0 = sl * 45, n1 = n0 + 45;
                    if (tid < 192) {
                        float m = -1e30f;
                        for (int n = n0; n < n1; n++) m = fmaxf(m, C[n * 52 + t]);
                        redM[sl * 48 + t] = m;
                    }
                    __syncthreads();
                    if (tid < 192) {
                        float mm = fmaxf(fmaxf(redM[t], redM[48 + t]),
                                         fmaxf(redM[96 + t], redM[144 + t]));
                        float s = 0.f;
                        for (int n = n0; n < n1; n++) {
                            float e = ex2f((C[n * 52 + t] - mm) * LOG2E);
                            C[n * 52 + t] = e;
                            s += e;
                        }
                        redS[sl * 48 + t] = s;
                    }
                    __syncthreads();
                    if (tid < 192) {
                        float inv = 1.f / (redS[t] + redS[48 + t] + redS[96 + t] + redS[144 + t]);
                        for (int n = n0; n < n1; n++) {
                            float v = C[n * 52 + t] * inv;
                            __nv_bfloat16 h = __float2bfloat16(v);
                            __nv_bfloat16 l = __float2bfloat16(v - __bfloat162float(h));
                            *(__nv_bfloat16*)(sm + OA + t * 400 + n * 2) = h;          // A(t, k=n)
                            *(__nv_bfloat16*)(sm + OA + APL + t * 400 + n * 2) = l;
                        }
                    }
                    // next chunk's post-wait __syncthreads orders these A writes vs ldmatrix
                } else {
                    for (int i = tid; i < 48 * 180; i += 256) {
                        int t = i / 180, n = i % 180;
                        g_hdec[((size_t)b * 240 + t0 + t) * 180 + n] = C[n * 52 + t];
                    }
                }
            }
        }
    }
}

// ---------------- output GEMM, split-K partials (unchanged, known-correct) ----------------
__device__ __forceinline__ ull ffma2(ull a, ull b, ull c) {
    ull d;
    asm("fma.rn.f32x2 %0, %1, %2, %3;" : "=l"(d) : "l"(a), "l"(b), "l"(c));
    return d;
}
__device__ __forceinline__ float2 unpackf2(ull v) {
    float2 r;
    asm("mov.b64 {%0, %1}, %2;" : "=f"(r.x), "=f"(r.y) : "l"(v));
    return r;
}

__global__ void __launch_bounds__(256) out_gemm(const float* __restrict__ Wout) {
    __shared__ float Hc[64][62];
    __shared__ float Wc[40][62];
    const int ks = blockIdx.x;
    const int b0 = blockIdx.y * 64;
    const int k0 = ks * 2700;
    const int tid = threadIdx.x;
    const int bg = tid % 32;
    const int ng = tid / 32;

    ull acc2[2][5];
#pragma unroll
    for (int bi = 0; bi < 2; bi++)
#pragma unroll
        for (int q = 0; q < 5; q++) acc2[bi][q] = 0ull;

    for (int cc = 0; cc < 45; cc++) {
        __syncthreads();
        const int kb = k0 + cc * 60;
        for (int i = tid; i < 64 * 60; i += 256) {
            int bb = i / 60, k = i % 60;
            Hc[bb][k] = g_hdec[(size_t)(b0 + bb) * 43200 + kb + k];
        }
        for (int i = tid; i < 40 * 60; i += 256) {
            int n = i / 60, k = i % 60;
            Wc[n][k] = Wout[(size_t)n * 43200 + kb + k];
        }
        __syncthreads();
#pragma unroll 6
        for (int kp = 0; kp < 30; kp++) {
            ull h0 = *(const ull*)&Hc[bg][kp * 2];
            ull h1 = *(const ull*)&Hc[bg + 32][kp * 2];
#pragma unroll
            for (int q = 0; q < 5; q++) {
                ull w = *(const ull*)&Wc[ng * 5 + q][kp * 2];
                acc2[0][q] = ffma2(h0, w, acc2[0][q]);
                acc2[1][q] = ffma2(h1, w, acc2[1][q]);
            }
        }
    }
#pragma unroll
    for (int bi = 0; bi < 2; bi++)
#pragma unroll
        for (int q = 0; q < 5; q++) {
            float2 p = unpackf2(acc2[bi][q]);
            g_part[((size_t)ks * 2048 + b0 + bg + 32 * bi) * 40 + ng * 5 + q] = p.x + p.y;
        }
}

__global__ void reduce_softmax(const float* __restrict__ bout, float* __restrict__ out) {
    __shared__ float smv[40];
    const int b = blockIdx.x;
    const int n = threadIdx.x;
    float l = bout[n];
#pragma unroll
    for (int ks = 0; ks < 16; ks++) l += g_part[((size_t)ks * 2048 + b) * 40 + n];
    smv[n] = l;
    __syncthreads();
    const int g0 = (n / 10) * 10;
    float m = smv[g0];
#pragma unroll
    for (int i = 1; i < 10; i++) m = fmaxf(m, smv[g0 + i]);
    float s = 0.f;
#pragma unroll
    for (int i = 0; i < 10; i++) s += expf(smv[g0 + i] - m);
    out[(size_t)b * 40 + n] = expf(l - m) / s;
}

// ---------------- launcher ----------------
extern "C" void kernel_launch(void* const* d_in, const int* in_sizes, int n_in,
                              void* d_out, int out_size) {
    const float* x    = (const float*)d_in[0];
    const float* Wenc = (const float*)d_in[1];
    const float* bie  = (const float*)d_in[2];
    const float* bhe  = (const float*)d_in[3];
    const float* Wdec = (const float*)d_in[4];
    const float* bid  = (const float*)d_in[5];
    const float* bhd  = (const float*)d_in[6];
    const float* Wout = (const float*)d_in[7];
    const float* bout = (const float*)d_in[8];
    float* out = (float*)d_out;

    cudaFuncSetAttribute(fused_encdec, cudaFuncAttributeMaxDynamicSharedMemorySize, SMEM_TOT);

    prep_weights<<<256, 256>>>(Wenc, bie, bhe, Wdec, bid, bhd);
    fused_encdec<<<dim3(5, 2048), 256, SMEM_TOT>>>(x);
    out_gemm<<<dim3(16, 32), 256>>>(Wout);
    reduce_softmax<<<2048, 40>>>(bout, out);
}

// round 9
// speedup vs baseline: 4.4965x; 1.6715x over previous
#include <cuda_runtime.h>
#include <cuda_bf16.h>
#include <math.h>
#include <stdint.h>

typedef unsigned long long ull;

// ===================== helpers =====================
__device__ __forceinline__ uint32_t smem_u32(const void* p) {
    uint32_t a;
    asm("{ .reg .u64 t; cvta.to.shared.u64 t, %1; cvt.u32.u64 %0, t; }" : "=r"(a) : "l"(p));
    return a;
}

#define LOG2E 1.4426950408889634f
__device__ __forceinline__ float ex2f(float x) { float r; asm("ex2.approx.ftz.f32 %0, %1;" : "=f"(r) : "f"(x)); return r; }
__device__ __forceinline__ float rcpf(float x) { float r; asm("rcp.approx.ftz.f32 %0, %1;" : "=f"(r) : "f"(x)); return r; }
__device__ __forceinline__ float sigf(float x)  { return rcpf(1.f + ex2f(-x * LOG2E)); }
__device__ __forceinline__ float tanhf_(float x) { return 2.f * rcpf(1.f + ex2f(-2.f * x * LOG2E)) - 1.f; }

// mma.sync m16n8k16 bf16 (sm_80+, no arch suffix)
__device__ __forceinline__ void mma16816(float* c, const uint32_t* a, const uint32_t* b) {
    asm volatile(
        "mma.sync.aligned.m16n8k16.row.col.f32.bf16.bf16.f32 "
        "{%0,%1,%2,%3}, {%4,%5,%6,%7}, {%8,%9}, {%0,%1,%2,%3};"
        : "+f"(c[0]), "+f"(c[1]), "+f"(c[2]), "+f"(c[3])
        : "r"(a[0]), "r"(a[1]), "r"(a[2]), "r"(a[3]), "r"(b[0]), "r"(b[1]));
}
#define LDSM4(r, a) \
    asm volatile("ldmatrix.sync.aligned.m8n8.x4.shared.b16 {%0,%1,%2,%3}, [%4];" \
        : "=r"((r)[0]), "=r"((r)[1]), "=r"((r)[2]), "=r"((r)[3]) : "r"(a))
#define LDSM2(r, a) \
    asm volatile("ldmatrix.sync.aligned.m8n8.x2.shared.b16 {%0,%1}, [%2];" \
        : "=r"((r)[0]), "=r"((r)[1]) : "r"(a))

#define CP16(dst, src) \
    asm volatile("cp.async.cg.shared.global [%0], [%1], 16;" :: "r"(dst), "l"(src) : "memory")
#define CP_COMMIT() asm volatile("cp.async.commit_group;" ::: "memory")
#define CP_WAIT1()  asm volatile("cp.async.wait_group 1;" ::: "memory")
#define CP_WAIT0()  asm volatile("cp.async.wait_group 0;" ::: "memory")

// ===================== global scratch =====================
// packed weights: [matgate 6][plane hi/lo][n 192][k 192] bf16 (only hi plane staged now)
__device__ __nv_bfloat16 g_Wpk[6 * 2 * 192 * 192];
__device__ float g_bias[6 * 192];            // [matgate][n], zero-padded
__device__ __nv_bfloat16 g_hdec[88473600];   // [2048][240][180] bf16
__device__ float g_part[16 * 2048 * 40];

// ===================== smem layout (bytes) =====================
// A: 2 planes x [48 rows][200 bf16] (400B rows)
#define OA    0
#define APL   19200
// B: 2 slots x [192 n][40 bf16] (80B rows = 32 k-vals + 16B pad), hi plane only
#define OB    38400
#define BSLOT 15360
// cbuf: [192 n][52 t] fp32 (writes conflict-free)
#define OC    69120
// red: redM[192], redS[192]
#define ORED  109056
#define SMEM_TOT 110592

// ===================== prep: pack weights (bf16 hi/lo planes) + bias =====================
__global__ void prep_weights(const float* __restrict__ We, const float* __restrict__ bie,
                             const float* __restrict__ bhe, const float* __restrict__ Wd,
                             const float* __restrict__ bid, const float* __restrict__ bhd) {
    const int gb[3] = {0, 360, 540};   // torch gates i,f,g,o -> keep i,g,o (f dead: c_prev=0)
    int idx = blockIdx.x * blockDim.x + threadIdx.x;
    int stride = gridDim.x * blockDim.x;
    for (int i = idx; i < 6 * 192 * 192; i += stride) {
        int k = i % 192, n = (i / 192) % 192, g = (i / 36864) % 3, mat = i / 110592;
        float v = 0.f;
        if (n < 180 && k < 180) v = (mat ? Wd : We)[(gb[g] + n) * 180 + k];
        __nv_bfloat16 h = __float2bfloat16(v);
        __nv_bfloat16 l = __float2bfloat16(v - __bfloat162float(h));
        size_t base = (size_t)(mat * 3 + g) * 2 * 36864 + (size_t)n * 192 + k;
        g_Wpk[base] = h;
        g_Wpk[base + 36864] = l;
    }
    for (int i = idx; i < 6 * 192; i += stride) {
        int n = i % 192, g = (i / 192) % 3, mat = i / 576;
        float v = 0.f;
        if (n < 180) v = (mat ? bid : bie)[gb[g] + n] + (mat ? bhd : bhe)[gb[g] + n];
        g_bias[(mat * 3 + g) * 192 + n] = v;
    }
}

// ===================== B chunk staging (k32, hi plane only) =====================
__device__ __forceinline__ void stage_chunk(uint32_t sb, int tid, int c) {
    int mg = c / 6, kc = c % 6;              // matgate 0..5, k-chunk 0..5
    const char* base = (const char*)g_Wpk + (size_t)mg * 147456;   // plane 0 = hi
    uint32_t dstb = sb + OB + (uint32_t)(c & 1) * BSLOT;
#pragma unroll
    for (int it = 0; it < 3; it++) {
        int idx = tid + it * 256;            // 0..767
        int j = idx & 3;                     // 16B piece within 64B row chunk
        int n = idx >> 2;                    // 0..191
        const void* src = base + (size_t)n * 384 + kc * 64 + j * 16;
        uint32_t dst = dstb + (uint32_t)n * 80 + (uint32_t)j * 16;
        CP16(dst, src);
    }
}

// ===================== fused enc -> softmax -> dec =====================
__global__ void __launch_bounds__(256, 2) fused_encdec(const float* __restrict__ x) {
    extern __shared__ char sm[];
    const uint32_t sb = smem_u32(sm);
    float* C = (float*)(sm + OC);
    float* redM = (float*)(sm + ORED);
    float* redS = redM + 192;
    const int tid = threadIdx.x, lane = tid & 31, wid = tid >> 5;
    const int b = blockIdx.y, t0 = blockIdx.x * 48;

    // Build A planes from x[b][k][t0+t]
    for (int i = tid; i < 192 * 48; i += 256) {
        int k = i / 48, t = i % 48;
        float v = (k < 180) ? x[((size_t)b * 180 + k) * 240 + t0 + t] : 0.f;
        __nv_bfloat16 h = __float2bfloat16(v);
        __nv_bfloat16 l = __float2bfloat16(v - __bfloat162float(h));
        *(__nv_bfloat16*)(sm + OA + t * 400 + k * 2) = h;
        *(__nv_bfloat16*)(sm + OA + APL + t * 400 + k * 2) = l;
    }

    // ldmatrix per-lane offsets
    const int rit = lane & 7, grp = lane >> 3;
    const uint32_t aoff = (uint32_t)((rit + (grp & 1) * 8) * 400 + (grp >> 1) * 16);
    const int l2 = lane & 15;
    const uint32_t boff = (uint32_t)((l2 & 7) * 80 + (l2 >> 3) * 16);

    stage_chunk(sb, tid, 0);
    CP_COMMIT();

    int c = 0;
    float sval[36];
    for (int mat = 0; mat < 2; mat++) {
        for (int g = 0; g < 3; g++) {
            float acc[36];
#pragma unroll
            for (int v = 0; v < 36; v++) acc[v] = 0.f;

            for (int kc = 0; kc < 6; kc++, c++) {
                if (c + 1 < 36) { stage_chunk(sb, tid, c + 1); CP_COMMIT(); CP_WAIT1(); }
                else CP_WAIT0();
                __syncthreads();   // chunk c visible; also orders A-plane writes
                uint32_t Bbase = sb + OB + (uint32_t)(c & 1) * BSLOT;
#pragma unroll
                for (int s = 0; s < 2; s++) {
                    const int k0 = kc * 32 + s * 16;       // global k for A
                    uint32_t Ah[3][4], Al[3][4];
#pragma unroll
                    for (int mi = 0; mi < 3; mi++) {
                        uint32_t a = sb + OA + (uint32_t)(mi * 6400) + (uint32_t)(k0 * 2) + aoff;
                        LDSM4(Ah[mi], a);
                        LDSM4(Al[mi], a + APL);
                    }
                    uint32_t Bh[3][2];
#pragma unroll
                    for (int ni = 0; ni < 3; ni++) {
                        uint32_t ba = Bbase + (uint32_t)((wid * 24 + ni * 8) * 80) +
                                      (uint32_t)(s * 32) + boff;
                        LDSM2(Bh[ni], ba);
                    }
#pragma unroll
                    for (int mi = 0; mi < 3; mi++)
#pragma unroll
                        for (int ni = 0; ni < 3; ni++) {
                            float* cc = &acc[(mi * 3 + ni) * 4];
                            mma16816(cc, Ah[mi], Bh[ni]);   // hi*hi
                            mma16816(cc, Al[mi], Bh[ni]);   // lo*hi
                        }
                }
                __syncthreads();   // all warps done with slot (c&1) before restage
            }

            // ---- gate epilogue (thread<->element mapping identical across gates) ----
            const float* bias = g_bias + (mat * 3 + g) * 192;
#pragma unroll
            for (int mi = 0; mi < 3; mi++)
#pragma unroll
                for (int ni = 0; ni < 3; ni++) {
                    int nb = wid * 24 + ni * 8 + (lane & 3) * 2;
                    float b0 = __ldg(bias + nb), b1 = __ldg(bias + nb + 1);
#pragma unroll
                    for (int r = 0; r < 4; r++) {
                        int v = (mi * 3 + ni) * 4 + r;
                        float bb = (r & 1) ? b1 : b0;
                        if (g == 0) {
                            sval[v] = sigf(acc[v] + bb);                       // sig(i)
                        } else if (g == 1) {
                            sval[v] = tanhf_(sval[v] * tanhf_(acc[v] + bb));   // tanh(c)
                        } else {
                            int t = mi * 16 + (lane >> 2) + ((r >> 1) & 1) * 8;
                            int n = nb + (r & 1);
                            C[n * 52 + t] = sigf(acc[v] + bb) * sval[v];       // h
                        }
                    }
                }

            if (g == 2) {
                __syncthreads();   // C complete
                if (mat == 0) {
                    // softmax over n per t; rewrite A planes with decoder input
                    int t = tid >> 2, sl = tid & 3, n0 = sl * 45, n1 = n0 + 45;
                    if (tid < 192) {
                        float m = -1e30f;
                        for (int n = n0; n < n1; n++) m = fmaxf(m, C[n * 52 + t]);
                        redM[sl * 48 + t] = m;
                    }
                    __syncthreads();
                    if (tid < 192) {
                        float mm = fmaxf(fmaxf(redM[t], redM[48 + t]),
                                         fmaxf(redM[96 + t], redM[144 + t]));
                        float s = 0.f;
                        for (int n = n0; n < n1; n++) {
                            float e = ex2f((C[n * 52 + t] - mm) * LOG2E);
                            C[n * 52 + t] = e;
                            s += e;
                        }
                        redS[sl * 48 + t] = s;
                    }
                    __syncthreads();
                    if (tid < 192) {
                        float inv = 1.f / (redS[t] + redS[48 + t] + redS[96 + t] + redS[144 + t]);
                        for (int n = n0; n < n1; n++) {
                            float v = C[n * 52 + t] * inv;
                            __nv_bfloat16 h = __float2bfloat16(v);
                            __nv_bfloat16 l = __float2bfloat16(v - __bfloat162float(h));
                            *(__nv_bfloat16*)(sm + OA + t * 400 + n * 2) = h;
                            *(__nv_bfloat16*)(sm + OA + APL + t * 400 + n * 2) = l;
                        }
                    }
                    // next chunk's post-wait __syncthreads orders these A writes vs ldmatrix
                } else {
                    for (int i = tid; i < 48 * 180; i += 256) {
                        int t = i / 180, n = i % 180;
                        g_hdec[((size_t)b * 240 + t0 + t) * 180 + n] =
                            __float2bfloat16(C[n * 52 + t]);
                    }
                }
            }
        }
    }
}

// ---------------- output GEMM, split-K partials (bf16 h loads) ----------------
__device__ __forceinline__ ull ffma2(ull a, ull b, ull c) {
    ull d;
    asm("fma.rn.f32x2 %0, %1, %2, %3;" : "=l"(d) : "l"(a), "l"(b), "l"(c));
    return d;
}
__device__ __forceinline__ float2 unpackf2(ull v) {
    float2 r;
    asm("mov.b64 {%0, %1}, %2;" : "=f"(r.x), "=f"(r.y) : "l"(v));
    return r;
}

__global__ void __launch_bounds__(256) out_gemm(const float* __restrict__ Wout) {
    __shared__ float Hc[64][62];
    __shared__ float Wc[40][62];
    const int ks = blockIdx.x;
    const int b0 = blockIdx.y * 64;
    const int k0 = ks * 2700;
    const int tid = threadIdx.x;
    const int bg = tid % 32;
    const int ng = tid / 32;

    ull acc2[2][5];
#pragma unroll
    for (int bi = 0; bi < 2; bi++)
#pragma unroll
        for (int q = 0; q < 5; q++) acc2[bi][q] = 0ull;

    for (int cc = 0; cc < 45; cc++) {
        __syncthreads();
        const int kb = k0 + cc * 60;
        for (int i = tid; i < 64 * 30; i += 256) {
            int bb = i / 30, k2 = i % 30;
            __nv_bfloat162 p = *(const __nv_bfloat162*)&g_hdec[(size_t)(b0 + bb) * 43200 + kb + k2 * 2];
            Hc[bb][k2 * 2]     = __bfloat162float(p.x);
            Hc[bb][k2 * 2 + 1] = __bfloat162float(p.y);
        }
        for (int i = tid; i < 40 * 60; i += 256) {
            int n = i / 60, k = i % 60;
            Wc[n][k] = Wout[(size_t)n * 43200 + kb + k];
        }
        __syncthreads();
#pragma unroll 6
        for (int kp = 0; kp < 30; kp++) {
            ull h0 = *(const ull*)&Hc[bg][kp * 2];
            ull h1 = *(const ull*)&Hc[bg + 32][kp * 2];
#pragma unroll
            for (int q = 0; q < 5; q++) {
                ull w = *(const ull*)&Wc[ng * 5 + q][kp * 2];
                acc2[0][q] = ffma2(h0, w, acc2[0][q]);
                acc2[1][q] = ffma2(h1, w, acc2[1][q]);
            }
        }
    }
#pragma unroll
    for (int bi = 0; bi < 2; bi++)
#pragma unroll
        for (int q = 0; q < 5; q++) {
            float2 p = unpackf2(acc2[bi][q]);
            g_part[((size_t)ks * 2048 + b0 + bg + 32 * bi) * 40 + ng * 5 + q] = p.x + p.y;
        }
}

__global__ void reduce_softmax(const float* __restrict__ bout, float* __restrict__ out) {
    __shared__ float smv[40];
    const int b = blockIdx.x;
    const int n = threadIdx.x;
    float l = bout[n];
#pragma unroll
    for (int ks = 0; ks < 16; ks++) l += g_part[((size_t)ks * 2048 + b) * 40 + n];
    smv[n] = l;
    __syncthreads();
    const int g0 = (n / 10) * 10;
    float m = smv[g0];
#pragma unroll
    for (int i = 1; i < 10; i++) m = fmaxf(m, smv[g0 + i]);
    float s = 0.f;
#pragma unroll
    for (int i = 0; i < 10; i++) s += expf(smv[g0 + i] - m);
    out[(size_t)b * 40 + n] = expf(l - m) / s;
}

// ---------------- launcher ----------------
extern "C" void kernel_launch(void* const* d_in, const int* in_sizes, int n_in,
                              void* d_out, int out_size) {
    const float* x    = (const float*)d_in[0];
    const float* Wenc = (const float*)d_in[1];
    const float* bie  = (const float*)d_in[2];
    const float* bhe  = (const float*)d_in[3];
    const float* Wdec = (const float*)d_in[4];
    const float* bid  = (const float*)d_in[5];
    const float* bhd  = (const float*)d_in[6];
    const float* Wout = (const float*)d_in[7];
    const float* bout = (const float*)d_in[8];
    float* out = (float*)d_out;

    cudaFuncSetAttribute(fused_encdec, cudaFuncAttributeMaxDynamicSharedMemorySize, SMEM_TOT);

    prep_weights<<<256, 256>>>(Wenc, bie, bhe, Wdec, bid, bhd);
    fused_encdec<<<dim3(5, 2048), 256, SMEM_TOT>>>(x);
    out_gemm<<<dim3(16, 32), 256>>>(Wout);
    reduce_softmax<<<2048, 40>>>(bout, out);
}